// round 11
// baseline (speedup 1.0000x reference)
#include <cuda_runtime.h>

// ComplexityAnalyzer: per-image 64-bin histogram + L1 normalize + 64->32->128 MLP.
// Inputs: grad_map [B*512*512] f32, W1 [32*64], b1 [32], W2 [128*32], b2 [128].
// Output: [B*128] f32.
//
// R10: R2's exact structure (grid=B, 1024 thr, __ldg unroll-4 static loop,
// per-warp smem hist + atomics), but the atomics are restructured:
//  - hist packed 2 bins/word (16-bit fields) -> 32 words/warp = 1 word per
//    bank, zero bank conflicts on any access pattern;
//  - __match_any_sync dedup on word index: one spread-address atomic per
//    distinct word per warp-batch (~20 of 32), leader adds (hi<<16)+lo
//    aggregated from two popcounts.

#define THREADS 1024
#define WARPS   32
#define HWORDS  32          // 32 packed words = 64 bins, one word per bank

__global__ __launch_bounds__(THREADS, 1)
void ca_hist_mlp_kernel(const float* __restrict__ grad,
                        const float* __restrict__ W1, const float* __restrict__ b1,
                        const float* __restrict__ W2, const float* __restrict__ b2,
                        float* __restrict__ out)
{
    __shared__ unsigned int hist[WARPS * HWORDS];   // 4 KB
    __shared__ float fh[64];
    __shared__ float hmid[32];
    __shared__ float inv_s;

    const int tid  = threadIdx.x;
    const int wid  = tid >> 5;
    const int lane = tid & 31;
    const int img  = blockIdx.x;

    // Zero per-warp packed histograms
    #pragma unroll
    for (int i = tid; i < WARPS * HWORDS; i += THREADS)
        hist[i] = 0u;
    __syncthreads();

    unsigned int* myh = hist + wid * HWORDS;
    const float4* src = (const float4*)(grad + (size_t)img * 262144u) + tid;

    const float scale = 64.0f / 255.0f;
    const float magic = 8388608.0f;  // 2^23

    // One element: bin = low mantissa of fma.rz(v,64/255,2^23) in [0,63].
    // word = bin>>1, half = bin&1. Dedup by word; leader adds packed counts.
    #define PROC1(x)                                                              \
        do {                                                                      \
            float q;                                                              \
            asm("fma.rz.f32 %0, %1, %2, %3;" : "=f"(q) : "f"(x), "f"(scale), "f"(magic)); \
            unsigned bin  = __float_as_uint(q) & 0x3Fu;                           \
            unsigned word = bin >> 1;                                             \
            unsigned mask = __match_any_sync(0xFFFFFFFFu, word);                  \
            unsigned bal  = __ballot_sync(0xFFFFFFFFu, bin & 1u);                 \
            unsigned hi   = __popc(mask & bal);                                   \
            unsigned tot  = __popc(mask);                                         \
            if ((int)lane == __ffs(mask) - 1)                                     \
                atomicAdd(&myh[word], (hi << 16) + (tot - hi));                   \
        } while (0)

    #pragma unroll 4
    for (int it = 0; it < 64; ++it) {
        float4 v = __ldg(&src[it * THREADS]);
        PROC1(v.x);
        PROC1(v.y);
        PROC1(v.z);
        PROC1(v.w);
    }
    __syncthreads();

    // Reduce: bin b lives in half (b&1) of word (b>>1) across 32 warp hists.
    if (tid < 64) {
        const int word = tid >> 1;
        const int sh   = (tid & 1) << 4;
        unsigned s = 0;
        #pragma unroll
        for (int w = 0; w < WARPS; ++w)
            s += (hist[w * HWORDS + word] >> sh) & 0xFFFFu;
        fh[tid] = (float)s;
    }
    __syncthreads();

    // L1 norm denominator
    if (tid < 32) {
        float s = fh[tid] + fh[tid + 32];
        #pragma unroll
        for (int off = 16; off > 0; off >>= 1)
            s += __shfl_down_sync(0xFFFFFFFFu, s, off);
        if (tid == 0) inv_s = 1.0f / fmaxf(s, 1e-12f);
    }
    __syncthreads();
    if (tid < 64) fh[tid] *= inv_s;
    __syncthreads();

    // Layer 1: 64 -> 32 with ReLU
    if (tid < 32) {
        float acc = b1[tid];
        const float* w = W1 + tid * 64;
        #pragma unroll
        for (int b = 0; b < 64; ++b) acc = fmaf(fh[b], w[b], acc);
        hmid[tid] = fmaxf(acc, 0.0f);
    }
    __syncthreads();

    // Layer 2: 32 -> 128
    if (tid < 128) {
        float acc = b2[tid];
        const float* w = W2 + tid * 32;
        #pragma unroll
        for (int j = 0; j < 32; ++j) acc = fmaf(hmid[j], w[j], acc);
        out[img * 128 + tid] = acc;
    }
}

extern "C" void kernel_launch(void* const* d_in, const int* in_sizes, int n_in,
                              void* d_out, int out_size) {
    const float* grad = (const float*)d_in[0];
    const float* W1   = (const float*)d_in[1];
    const float* b1   = (const float*)d_in[2];
    const float* W2   = (const float*)d_in[3];
    const float* b2   = (const float*)d_in[4];
    float* out = (float*)d_out;

    int B = in_sizes[0] / (512 * 512);
    ca_hist_mlp_kernel<<<B, THREADS>>>(grad, W1, b1, W2, b2, out);
}

// round 12
// speedup vs baseline: 4.7548x; 4.7548x over previous
#include <cuda_runtime.h>

// ComplexityAnalyzer: per-image 64-bin histogram + L1 normalize + 64->32->128 MLP.
// Inputs: grad_map [B*512*512] f32, W1 [32*64], b1 [32], W2 [128*32], b2 [128].
// Output: [B*128] f32.
//
// R12: R2's exact per-element machinery (per-warp smem hist + atomics, __ldg
// unroll-4 STATIC loop) spread over 148 SMs via a flat block split with
// COMPILE-TIME trip counts (56/55 via template dispatch). Image-boundary
// crossing handled with two hist banks + per-iteration uniform pointer SEL
// (no mid-loop flush). Per-image completion via global hist + done counter;
// finishing CTA runs the MLP and self-cleans scratch (graph-replay safe).

#define THREADS 1024
#define WARPS   32
#define NPAD    66            // 65 live bins (0..63 + catch 64), padded
#define HBANK   (WARPS * NPAD)
#define BLK_F4  1024          // float4 per block (1 per thread per iter)
#define BPI     64            // blocks per image (65536 F4)
#define MAX_IMG 256

__device__ unsigned int g_hist[MAX_IMG * 64];   // zero-init; self-cleaning
__device__ unsigned int g_done[MAX_IMG];        // zero-init; self-cleaning

__device__ __forceinline__ void hist_elem(unsigned int* h, float x,
                                          float scale, float magic) {
    float q;
    asm("fma.rz.f32 %0, %1, %2, %3;" : "=f"(q) : "f"(x), "f"(scale), "f"(magic));
    unsigned b = min(__float_as_uint(q) & 0x7Fu, 64u);
    atomicAdd(&h[b], 1u);
}

template <int NBLK>
__device__ __forceinline__ void count_static(const float4* __restrict__ p,
                                             unsigned int* myhA,
                                             unsigned int* myhB, int itB) {
    const float scale = 64.0f / 255.0f;
    const float magic = 8388608.0f;  // 2^23
    #pragma unroll 4
    for (int it = 0; it < NBLK; ++it) {
        float4 v = __ldg(&p[it * BLK_F4]);
        unsigned int* h = (it >= itB) ? myhB : myhA;   // uniform SEL
        hist_elem(h, v.x, scale, magic);
        hist_elem(h, v.y, scale, magic);
        hist_elem(h, v.z, scale, magic);
        hist_elem(h, v.w, scale, magic);
    }
}

__device__ __forceinline__ void count_dyn(const float4* __restrict__ p,
                                          unsigned int* myhA,
                                          unsigned int* myhB, int itB, int nBlk) {
    const float scale = 64.0f / 255.0f;
    const float magic = 8388608.0f;
    #pragma unroll 4
    for (int it = 0; it < nBlk; ++it) {
        float4 v = __ldg(&p[it * BLK_F4]);
        unsigned int* h = (it >= itB) ? myhB : myhA;
        hist_elem(h, v.x, scale, magic);
        hist_elem(h, v.y, scale, magic);
        hist_elem(h, v.z, scale, magic);
        hist_elem(h, v.w, scale, magic);
    }
}

struct MlpSmem { float fh[64]; float hmid[32]; float inv_s; };

__device__ __forceinline__ void run_mlp(int img, int tid, MlpSmem& s,
                                        const float* __restrict__ W1,
                                        const float* __restrict__ b1,
                                        const float* __restrict__ W2,
                                        const float* __restrict__ b2,
                                        float* __restrict__ out) {
    if (tid < 64) {
        __threadfence();                                 // acquire
        s.fh[tid] = (float)atomicAdd(&g_hist[img * 64 + tid], 0u);
    }
    __syncthreads();
    if (tid < 32) {
        float t = s.fh[tid] + s.fh[tid + 32];
        #pragma unroll
        for (int off = 16; off > 0; off >>= 1)
            t += __shfl_down_sync(0xFFFFFFFFu, t, off);
        if (tid == 0) s.inv_s = 1.0f / fmaxf(t, 1e-12f);
    }
    __syncthreads();
    if (tid < 64) s.fh[tid] *= s.inv_s;
    __syncthreads();
    if (tid < 32) {
        float acc = b1[tid];
        const float* w = W1 + tid * 64;
        #pragma unroll
        for (int b = 0; b < 64; ++b) acc = fmaf(s.fh[b], w[b], acc);
        s.hmid[tid] = fmaxf(acc, 0.0f);
    }
    __syncthreads();
    if (tid < 128) {
        float acc = b2[tid];
        const float* w = W2 + tid * 32;
        #pragma unroll
        for (int j = 0; j < 32; ++j) acc = fmaf(s.hmid[j], w[j], acc);
        out[img * 128 + tid] = acc;
    }
    // self-clean scratch for deterministic graph replays
    if (tid < 64) atomicExch(&g_hist[img * 64 + tid], 0u);
    if (tid == 0) atomicExch(&g_done[img], 0u);
    __syncthreads();
}

__global__ __launch_bounds__(THREADS, 1)
void ca_hist_mlp_kernel(const float* __restrict__ grad,
                        const float* __restrict__ W1, const float* __restrict__ b1,
                        const float* __restrict__ W2, const float* __restrict__ b2,
                        float* __restrict__ out, int totalBlocks)
{
    __shared__ unsigned int hist[2 * HBANK];   // two banks (imgA / imgB), ~16.9 KB
    __shared__ MlpSmem ms;
    __shared__ int sh_doA, sh_doB;

    const int tid = threadIdx.x;
    const int wid = tid >> 5;

    // Flat split: CTA c gets base + (c < rem) contiguous blocks.
    const int nCta = gridDim.x;
    const int base = totalBlocks / nCta;
    const int rem  = totalBlocks % nCta;
    const int b0   = blockIdx.x * base + min((int)blockIdx.x, rem);
    const int nBlk = base + ((int)blockIdx.x < rem ? 1 : 0);

    const int imgA = b0 / BPI;
    const int itB  = min((imgA + 1) * BPI - b0, nBlk);   // iters in imgA
    const int blocksA = itB;
    const int blocksB = nBlk - itB;
    const int imgB = imgA + 1;

    // Zero both hist banks
    #pragma unroll
    for (int i = tid; i < 2 * HBANK; i += THREADS)
        hist[i] = 0u;
    __syncthreads();

    unsigned int* myhA = hist + wid * NPAD;
    unsigned int* myhB = myhA + HBANK;
    const float4* p = (const float4*)grad + (size_t)b0 * BLK_F4 + tid;

    if (nBlk == 56)      count_static<56>(p, myhA, myhB, itB);
    else if (nBlk == 55) count_static<55>(p, myhA, myhB, itB);
    else if (nBlk == 64) count_static<64>(p, myhA, myhB, itB);
    else                 count_dyn(p, myhA, myhB, itB, nBlk);
    __syncthreads();

    // Reduce + flush both banks in parallel: tid 0-63 bank A, 64-127 bank B.
    if (tid < 128) {
        const int bankB = tid >> 6;
        const int bin   = tid & 63;
        if (!bankB || blocksB > 0) {
            const unsigned int* hb = hist + bankB * HBANK;
            unsigned s = 0;
            #pragma unroll
            for (int w = 0; w < WARPS; ++w)
                s += hb[w * NPAD + bin];
            if (bin == 63) {                  // fold catch bin 64 (v==VMAX) into 63
                #pragma unroll
                for (int w = 0; w < WARPS; ++w)
                    s += hb[w * NPAD + 64];
            }
            const int im = bankB ? imgB : imgA;
            if (s) atomicAdd(&g_hist[im * 64 + bin], s);
        }
        __threadfence();                      // release before done-count
    }
    __syncthreads();

    if (tid == 0) {
        unsigned old = atomicAdd(&g_done[imgA], (unsigned)blocksA);
        sh_doA = (old + (unsigned)blocksA == (unsigned)BPI);
    }
    if (tid == 1) {
        int d = 0;
        if (blocksB > 0) {
            unsigned old = atomicAdd(&g_done[imgB], (unsigned)blocksB);
            d = (old + (unsigned)blocksB == (unsigned)BPI);
        }
        sh_doB = d;
    }
    __syncthreads();

    if (sh_doA) run_mlp(imgA, tid, ms, W1, b1, W2, b2, out);
    if (sh_doB) run_mlp(imgB, tid, ms, W1, b1, W2, b2, out);
}

extern "C" void kernel_launch(void* const* d_in, const int* in_sizes, int n_in,
                              void* d_out, int out_size) {
    const float* grad = (const float*)d_in[0];
    const float* W1   = (const float*)d_in[1];
    const float* b1   = (const float*)d_in[2];
    const float* W2   = (const float*)d_in[3];
    const float* b2   = (const float*)d_in[4];
    float* out = (float*)d_out;

    int totalBlocks = in_sizes[0] / (4 * BLK_F4);
    int nCta = totalBlocks < 148 ? totalBlocks : 148;
    ca_hist_mlp_kernel<<<nCta, THREADS>>>(grad, W1, b1, W2, b2, out, totalBlocks);
}

// round 14
// speedup vs baseline: 5.6219x; 1.1824x over previous
#include <cuda_runtime.h>

// ComplexityAnalyzer: per-image 64-bin histogram + L1 normalize + 64->32->128 MLP.
// Inputs: grad_map [B*512*512] f32, W1 [32*64], b1 [32], W2 [128*32], b2 [128].
// Output: [B*128] f32.
//
// R13: R2's proven shape (grid=B, 1024 thr, __ldg unroll-4 static loop) with
// CONFLICT-FREE shared atomics: per-warp lane-transposed counter region
// cnt[wid][word][lane] (lane l -> bank l always), 2 bins packed per word as
// 16-bit fields. Atomics resolve the RMW hazard in HW (no compiler-serialized
// LDS chains like R6/R9) and never bank-conflict (unlike R2's bin-addressed
// hist, measured ~3.4 passes). 256 elems/thread < 65536 -> no overflow, no
// mid-loop flush. End: conflict-free transpose-reduce + tiny MLP.

#define THREADS 1024
#define WARPS   32
#define WORDS   32                       // 32 words x 2 packed bins = 64 bins
#define CNT_WORDS (WARPS * WORDS * 32)   // 32K words = 128 KB

__global__ __launch_bounds__(THREADS, 1)
void ca_hist_mlp_kernel(const float* __restrict__ grad,
                        const float* __restrict__ W1, const float* __restrict__ b1,
                        const float* __restrict__ W2, const float* __restrict__ b2,
                        float* __restrict__ out)
{
    extern __shared__ unsigned int cnt[];   // [32 warps][32 words][32 lanes]
    __shared__ float fh[64];
    __shared__ float hmid[32];
    __shared__ float inv_s;

    const int tid  = threadIdx.x;
    const int wid  = tid >> 5;
    const int lane = tid & 31;
    const int img  = blockIdx.x;

    // Zero 128 KB of counters (vector stores, conflict-free)
    {
        uint4 z = {0u, 0u, 0u, 0u};
        uint4* p = (uint4*)cnt;
        #pragma unroll
        for (int i = tid; i < CNT_WORDS / 4; i += THREADS)
            p[i] = z;
    }
    __syncthreads();

    // Per-thread base: my warp's region, my lane's column (bank == lane).
    unsigned int* mybase = cnt + (wid << 10) + lane;
    const float4* src = (const float4*)(grad + (size_t)img * 262144u) + tid;

    const float scale = 64.0f / 255.0f;
    const float magic = 8388608.0f;  // 2^23

    // bin = low mantissa of fma.rz(v, 64/255, 2^23), strictly in [0,63]
    // (input < 255). word = bin>>1 -> offset ((m & 0x3E) << 4) in words;
    // 16-bit field select via (bin&1).
    #define PROC1(x)                                                              \
        do {                                                                      \
            float q;                                                              \
            asm("fma.rz.f32 %0, %1, %2, %3;" : "=f"(q) : "f"(x), "f"(scale), "f"(magic)); \
            unsigned m = __float_as_uint(q);                                      \
            unsigned inc = (m & 1u) ? 0x10000u : 1u;                              \
            atomicAdd(&mybase[(m & 0x3Eu) << 4], inc);                            \
        } while (0)

    #pragma unroll 4
    for (int it = 0; it < 64; ++it) {
        float4 v = __ldg(&src[it * THREADS]);
        PROC1(v.x);
        PROC1(v.y);
        PROC1(v.z);
        PROC1(v.w);
    }
    __syncthreads();

    // Transpose-reduce, conflict-free: thread (j=wid', lane) sums word j of
    // all 32 warp regions at its lane column -> packed pair totals; then warp
    // j shfl-reduces its 32 lane-partials into bins 2j and 2j+1.
    {
        const int j = wid;                 // word index 0..31
        unsigned tot = 0;
        const unsigned int* p = cnt + (j << 5) + lane;   // + w*1024 per warp
        #pragma unroll
        for (int w = 0; w < WARPS; ++w)
            tot += p[w << 10];
        unsigned lo = tot & 0xFFFFu;
        unsigned hi = tot >> 16;
        #pragma unroll
        for (int off = 16; off > 0; off >>= 1) {
            lo += __shfl_down_sync(0xFFFFFFFFu, lo, off);
            hi += __shfl_down_sync(0xFFFFFFFFu, hi, off);
        }
        if (lane == 0) {
            fh[2 * j + 0] = (float)lo;
            fh[2 * j + 1] = (float)hi;
        }
    }
    __syncthreads();

    // L1 norm denominator
    if (tid < 32) {
        float s = fh[tid] + fh[tid + 32];
        #pragma unroll
        for (int off = 16; off > 0; off >>= 1)
            s += __shfl_down_sync(0xFFFFFFFFu, s, off);
        if (tid == 0) inv_s = 1.0f / fmaxf(s, 1e-12f);
    }
    __syncthreads();
    if (tid < 64) fh[tid] *= inv_s;
    __syncthreads();

    // Layer 1: 64 -> 32 with ReLU
    if (tid < 32) {
        float acc = b1[tid];
        const float* w = W1 + tid * 64;
        #pragma unroll
        for (int b = 0; b < 64; ++b) acc = fmaf(fh[b], w[b], acc);
        hmid[tid] = fmaxf(acc, 0.0f);
    }
    __syncthreads();

    // Layer 2: 32 -> 128
    if (tid < 128) {
        float acc = b2[tid];
        const float* w = W2 + tid * 32;
        #pragma unroll
        for (int j2 = 0; j2 < 32; ++j2) acc = fmaf(hmid[j2], w[j2], acc);
        out[img * 128 + tid] = acc;
    }
}

extern "C" void kernel_launch(void* const* d_in, const int* in_sizes, int n_in,
                              void* d_out, int out_size) {
    const float* grad = (const float*)d_in[0];
    const float* W1   = (const float*)d_in[1];
    const float* b1   = (const float*)d_in[2];
    const float* W2   = (const float*)d_in[3];
    const float* b2   = (const float*)d_in[4];
    float* out = (float*)d_out;

    static int smem_set = 0;   // idempotent attribute (not a work guard)
    if (!smem_set) {
        cudaFuncSetAttribute(ca_hist_mlp_kernel,
                             cudaFuncAttributeMaxDynamicSharedMemorySize,
                             CNT_WORDS * 4);
        smem_set = 1;
    }

    int B = in_sizes[0] / (512 * 512);
    ca_hist_mlp_kernel<<<B, THREADS, CNT_WORDS * 4>>>(grad, W1, b1, W2, b2, out);
}

// round 15
// speedup vs baseline: 5.6277x; 1.0010x over previous
#include <cuda_runtime.h>

// ComplexityAnalyzer: per-image 64-bin histogram + L1 normalize + 64->32->128 MLP.
// Inputs: grad_map [B*512*512] f32, W1 [32*64], b1 [32], W2 [128*32], b2 [128].
// Output: [B*128] f32.
//
// R13: R2's proven shape (grid=B, 1024 thr, __ldg unroll-4 static loop) with
// CONFLICT-FREE shared atomics: per-warp lane-transposed counter region
// cnt[wid][word][lane] (lane l -> bank l always), 2 bins packed per word as
// 16-bit fields. Atomics resolve the RMW hazard in HW (no compiler-serialized
// LDS chains like R6/R9) and never bank-conflict (unlike R2's bin-addressed
// hist, measured ~3.4 passes). 256 elems/thread < 65536 -> no overflow, no
// mid-loop flush. End: conflict-free transpose-reduce + tiny MLP.

#define THREADS 1024
#define WARPS   32
#define WORDS   32                       // 32 words x 2 packed bins = 64 bins
#define CNT_WORDS (WARPS * WORDS * 32)   // 32K words = 128 KB

__global__ __launch_bounds__(THREADS, 1)
void ca_hist_mlp_kernel(const float* __restrict__ grad,
                        const float* __restrict__ W1, const float* __restrict__ b1,
                        const float* __restrict__ W2, const float* __restrict__ b2,
                        float* __restrict__ out)
{
    extern __shared__ unsigned int cnt[];   // [32 warps][32 words][32 lanes]
    __shared__ float fh[64];
    __shared__ float hmid[32];
    __shared__ float inv_s;

    const int tid  = threadIdx.x;
    const int wid  = tid >> 5;
    const int lane = tid & 31;
    const int img  = blockIdx.x;

    // Zero 128 KB of counters (vector stores, conflict-free)
    {
        uint4 z = {0u, 0u, 0u, 0u};
        uint4* p = (uint4*)cnt;
        #pragma unroll
        for (int i = tid; i < CNT_WORDS / 4; i += THREADS)
            p[i] = z;
    }
    __syncthreads();

    // Per-thread base: my warp's region, my lane's column (bank == lane).
    unsigned int* mybase = cnt + (wid << 10) + lane;
    const float4* src = (const float4*)(grad + (size_t)img * 262144u) + tid;

    const float scale = 64.0f / 255.0f;
    const float magic = 8388608.0f;  // 2^23

    // bin = low mantissa of fma.rz(v, 64/255, 2^23), strictly in [0,63]
    // (input < 255). word = bin>>1 -> offset ((m & 0x3E) << 4) in words;
    // 16-bit field select via (bin&1).
    #define PROC1(x)                                                              \
        do {                                                                      \
            float q;                                                              \
            asm("fma.rz.f32 %0, %1, %2, %3;" : "=f"(q) : "f"(x), "f"(scale), "f"(magic)); \
            unsigned m = __float_as_uint(q);                                      \
            unsigned inc = (m & 1u) ? 0x10000u : 1u;                              \
            atomicAdd(&mybase[(m & 0x3Eu) << 4], inc);                            \
        } while (0)

    #pragma unroll 4
    for (int it = 0; it < 64; ++it) {
        float4 v = __ldg(&src[it * THREADS]);
        PROC1(v.x);
        PROC1(v.y);
        PROC1(v.z);
        PROC1(v.w);
    }
    __syncthreads();

    // Transpose-reduce, conflict-free: thread (j=wid', lane) sums word j of
    // all 32 warp regions at its lane column -> packed pair totals; then warp
    // j shfl-reduces its 32 lane-partials into bins 2j and 2j+1.
    {
        const int j = wid;                 // word index 0..31
        unsigned tot = 0;
        const unsigned int* p = cnt + (j << 5) + lane;   // + w*1024 per warp
        #pragma unroll
        for (int w = 0; w < WARPS; ++w)
            tot += p[w << 10];
        unsigned lo = tot & 0xFFFFu;
        unsigned hi = tot >> 16;
        #pragma unroll
        for (int off = 16; off > 0; off >>= 1) {
            lo += __shfl_down_sync(0xFFFFFFFFu, lo, off);
            hi += __shfl_down_sync(0xFFFFFFFFu, hi, off);
        }
        if (lane == 0) {
            fh[2 * j + 0] = (float)lo;
            fh[2 * j + 1] = (float)hi;
        }
    }
    __syncthreads();

    // L1 norm denominator
    if (tid < 32) {
        float s = fh[tid] + fh[tid + 32];
        #pragma unroll
        for (int off = 16; off > 0; off >>= 1)
            s += __shfl_down_sync(0xFFFFFFFFu, s, off);
        if (tid == 0) inv_s = 1.0f / fmaxf(s, 1e-12f);
    }
    __syncthreads();
    if (tid < 64) fh[tid] *= inv_s;
    __syncthreads();

    // Layer 1: 64 -> 32 with ReLU
    if (tid < 32) {
        float acc = b1[tid];
        const float* w = W1 + tid * 64;
        #pragma unroll
        for (int b = 0; b < 64; ++b) acc = fmaf(fh[b], w[b], acc);
        hmid[tid] = fmaxf(acc, 0.0f);
    }
    __syncthreads();

    // Layer 2: 32 -> 128
    if (tid < 128) {
        float acc = b2[tid];
        const float* w = W2 + tid * 32;
        #pragma unroll
        for (int j2 = 0; j2 < 32; ++j2) acc = fmaf(hmid[j2], w[j2], acc);
        out[img * 128 + tid] = acc;
    }
}

extern "C" void kernel_launch(void* const* d_in, const int* in_sizes, int n_in,
                              void* d_out, int out_size) {
    const float* grad = (const float*)d_in[0];
    const float* W1   = (const float*)d_in[1];
    const float* b1   = (const float*)d_in[2];
    const float* W2   = (const float*)d_in[3];
    const float* b2   = (const float*)d_in[4];
    float* out = (float*)d_out;

    static int smem_set = 0;   // idempotent attribute (not a work guard)
    if (!smem_set) {
        cudaFuncSetAttribute(ca_hist_mlp_kernel,
                             cudaFuncAttributeMaxDynamicSharedMemorySize,
                             CNT_WORDS * 4);
        smem_set = 1;
    }

    int B = in_sizes[0] / (512 * 512);
    ca_hist_mlp_kernel<<<B, THREADS, CNT_WORDS * 4>>>(grad, W1, b1, W2, b2, out);
}